// round 10
// baseline (speedup 1.0000x reference)
#include <cuda_runtime.h>

#define EMB   64
#define NSPH  16
#define KMAX  24
#define MAX_EDGES 131072

__device__ int    g_start[MAX_EDGES];
__device__ int    g_count[MAX_EDGES];
// W in mma-fragment order, 2 kt-frags packed per float4:
// g_Wf4[(j*8+nt)*32 + lane] = {b0(kt=2j), b1(kt=2j), b0(kt=2j+1), b1(kt=2j+1)}
// where for frag (kt,nt): b0 = Wt[kt*8+tig][nt*8+gid], b1 = +4 rows (k8n8 col-major).
__device__ float4 g_Wf4[32 * 32];

__global__ void prep_kernel(const int* __restrict__ id_reduce,
                            const int* __restrict__ Kidx,
                            const float* __restrict__ w, int nT)
{
    int t = blockIdx.x * blockDim.x + threadIdx.x;
    if (t < 1024) {
        int entry = t >> 5, lane = t & 31;
        int j  = entry >> 3, nt = entry & 7;
        int gid = lane >> 2, tig = lane & 3;
        int d = nt * 8 + gid;
        float v[4];
        #pragma unroll
        for (int h = 0; h < 2; h++) {
            int i = (2 * j + h) * 8 + tig;
            float b0 = w[d * EMB + i];
            float b1 = w[d * EMB + i + 4];
            unsigned r0, r1;
            asm("cvt.rna.tf32.f32 %0, %1;" : "=r"(r0) : "f"(b0));
            asm("cvt.rna.tf32.f32 %0, %1;" : "=r"(r1) : "f"(b1));
            v[2 * h]     = __uint_as_float(r0);
            v[2 * h + 1] = __uint_as_float(r1);
        }
        g_Wf4[t] = make_float4(v[0], v[1], v[2], v[3]);
    }
    if (t < nT) {
        int e = id_reduce[t];
        if (t == 0 || id_reduce[t - 1] != e) g_start[e] = t;
        if (t == nT - 1 || id_reduce[t + 1] != e) g_count[e] = Kidx[t] + 1;
    }
}

__device__ __forceinline__ unsigned tf32r(float x) {
    unsigned u; asm("cvt.rna.tf32.f32 %0, %1;" : "=r"(u) : "f"(x)); return u;
}

__device__ __forceinline__ void mma_tf32(float c[4], const unsigned a[4],
                                         unsigned b0, unsigned b1)
{
    asm volatile(
        "mma.sync.aligned.m16n8k8.row.col.f32.tf32.tf32.f32 "
        "{%0,%1,%2,%3},{%4,%5,%6,%7},{%8,%9},{%0,%1,%2,%3};"
        : "+f"(c[0]), "+f"(c[1]), "+f"(c[2]), "+f"(c[3])
        : "r"(a[0]), "r"(a[1]), "r"(a[2]), "r"(a[3]), "r"(b0), "r"(b1));
}

// One warp per edge, fully front-loaded for MLP:
//   batch: sph frags (12) + ALL m B-frags (48, predicated) + rbf raw (32)
//          -> ~92 DRAM loads in flight before any compute.
//   Q phase: 24 mmas -> q[8][4] (mf dies as q grows).
//   cvt rbf -> P phase: per nt, 4 W float4 L1-hit loads + 8 mmas,
//   Hadamard vs q[nt], xor-shfl s-reduction, float2 store.
// No shared memory. launch_bounds caps regs at 128 -> 16 warps/SM.
__global__ void __launch_bounds__(256, 2)
main_kernel(const float* __restrict__ rbf,
            const float* __restrict__ sph,
            const float* __restrict__ m,
            float* __restrict__ out, int nEdges)
{
    const int lane = threadIdx.x & 31;
    const int gid  = lane >> 2;   // 0..7
    const int tig  = lane & 3;    // 0..3

    const int e = blockIdx.x * 8 + (threadIdx.x >> 5);
    if (e >= nEdges) return;

    const int st0 = g_start[e];
    const int ct0 = g_count[e];

    // ---- front-loaded batch 1: sph A-frags ----
    unsigned sa[3][4];
    {
        const float* s0 = sph + (size_t)e * (NSPH * KMAX);
        #pragma unroll
        for (int kt = 0; kt < 3; kt++) {
            int t = kt * 8 + tig;
            sa[kt][0] = tf32r(__ldg(&s0[gid * KMAX + t]));
            sa[kt][1] = tf32r(__ldg(&s0[(gid + 8) * KMAX + t]));
            sa[kt][2] = tf32r(__ldg(&s0[gid * KMAX + t + 4]));
            sa[kt][3] = tf32r(__ldg(&s0[(gid + 8) * KMAX + t + 4]));
        }
    }

    // ---- front-loaded batch 2: all m B-frags (predicated on t<count) ----
    unsigned mf[8][6];   // [nt][kt*2 + half]
    {
        const float* mb = m + (size_t)st0 * EMB + gid;
        #pragma unroll
        for (int nt = 0; nt < 8; nt++) {
            #pragma unroll
            for (int kt = 0; kt < 3; kt++) {
                int t = kt * 8 + tig;
                mf[nt][kt * 2 + 0] = (t < ct0)
                    ? tf32r(__ldg(mb + (size_t)t * EMB + nt * 8)) : 0u;
                mf[nt][kt * 2 + 1] = (t + 4 < ct0)
                    ? tf32r(__ldg(mb + (size_t)(t + 4) * EMB + nt * 8)) : 0u;
            }
        }
    }

    // ---- front-loaded batch 3: rbf A-frags, raw f32 (cvt deferred) ----
    float raf[8][4];
    {
        const float* r0 = rbf + (size_t)e * (EMB * NSPH);
        #pragma unroll
        for (int kt = 0; kt < 8; kt++) {
            int i = kt * 8 + tig;
            raf[kt][0] = __ldg(&r0[i * NSPH + gid]);
            raf[kt][1] = __ldg(&r0[i * NSPH + gid + 8]);
            raf[kt][2] = __ldg(&r0[(i + 4) * NSPH + gid]);
            raf[kt][3] = __ldg(&r0[(i + 4) * NSPH + gid + 8]);
        }
    }

    // ---- Q phase: all 8 tiles (rbf loads still in flight) ----
    float q[8][4];
    #pragma unroll
    for (int nt = 0; nt < 8; nt++) {
        q[nt][0] = q[nt][1] = q[nt][2] = q[nt][3] = 0.f;
        #pragma unroll
        for (int kt = 0; kt < 3; kt++)
            mma_tf32(q[nt], sa[kt], mf[nt][kt * 2], mf[nt][kt * 2 + 1]);
    }

    // ---- cvt rbf in place ----
    unsigned ra[8][4];
    #pragma unroll
    for (int kt = 0; kt < 8; kt++)
        #pragma unroll
        for (int r = 0; r < 4; r++)
            ra[kt][r] = tf32r(raf[kt][r]);

    // ---- P phase + Hadamard + s-reduction + store ----
    #pragma unroll
    for (int nt = 0; nt < 8; nt++) {
        float p0[4] = {0.f, 0.f, 0.f, 0.f};
        #pragma unroll
        for (int j = 0; j < 4; j++) {
            float4 wf = __ldg(&g_Wf4[(j * 8 + nt) * 32 + lane]);
            mma_tf32(p0, ra[2 * j],     __float_as_uint(wf.x), __float_as_uint(wf.y));
            mma_tf32(p0, ra[2 * j + 1], __float_as_uint(wf.z), __float_as_uint(wf.w));
        }

        // c0:(s=gid, d=2tig) c1:(gid, 2tig+1) c2:(gid+8, 2tig) c3:(gid+8, 2tig+1)
        float h00 = p0[0] * q[nt][0] + p0[2] * q[nt][2];
        float h01 = p0[1] * q[nt][1] + p0[3] * q[nt][3];
        #pragma unroll
        for (int off = 4; off <= 16; off <<= 1) {
            h00 += __shfl_xor_sync(0xffffffffu, h00, off);
            h01 += __shfl_xor_sync(0xffffffffu, h01, off);
        }
        if (gid == 0)
            *(float2*)(out + (size_t)e * EMB + nt * 8 + 2 * tig) = make_float2(h00, h01);
    }
}

extern "C" void kernel_launch(void* const* d_in, const int* in_sizes, int n_in,
                              void* d_out, int out_size)
{
    const float* rbf  = (const float*)d_in[0];
    const float* sph  = (const float*)d_in[1];
    const float* m    = (const float*)d_in[2];
    const float* w    = (const float*)d_in[3];
    const int*   idr  = (const int*)d_in[4];
    const int*   kidx = (const int*)d_in[5];

    const int nEdges = in_sizes[0] / (EMB * NSPH);
    const int nT     = in_sizes[4];

    int prep_elems = nT > 1024 ? nT : 1024;
    prep_kernel<<<(prep_elems + 255) / 256, 256>>>(idr, kidx, w, nT);

    main_kernel<<<(nEdges + 7) / 8, 256>>>(rbf, sph, m, (float*)d_out, nEdges);
}

// round 11
// speedup vs baseline: 1.1155x; 1.1155x over previous
#include <cuda_runtime.h>

#define EMB   64
#define NSPH  16
#define KMAX  24
#define MAX_EDGES 131072
#define MROW  72   // padded m row (floats): frag LDS bank = 8*(tig+nt)+gid, conflict-free
#define SROW  28   // padded sph row: bank = -4*gid + tig (+4), conflict-free

__device__ int    g_start[MAX_EDGES];
__device__ int    g_count[MAX_EDGES];
// W in mma-fragment order, 2 kt-frags packed per float4:
// g_Wf4[(j*8+nt)*32 + lane] = {b0(kt=2j), b1(kt=2j), b0(kt=2j+1), b1(kt=2j+1)}
__device__ float4 g_Wf4[32 * 32];

__global__ void prep_kernel(const int* __restrict__ id_reduce,
                            const int* __restrict__ Kidx,
                            const float* __restrict__ w, int nT)
{
    int t = blockIdx.x * blockDim.x + threadIdx.x;
    if (t < 1024) {
        int entry = t >> 5, lane = t & 31;
        int j  = entry >> 3, nt = entry & 7;
        int gid = lane >> 2, tig = lane & 3;
        int d = nt * 8 + gid;
        float v[4];
        #pragma unroll
        for (int h = 0; h < 2; h++) {
            int i = (2 * j + h) * 8 + tig;
            unsigned r0, r1;
            asm("cvt.rna.tf32.f32 %0, %1;" : "=r"(r0) : "f"(w[d * EMB + i]));
            asm("cvt.rna.tf32.f32 %0, %1;" : "=r"(r1) : "f"(w[d * EMB + i + 4]));
            v[2 * h]     = __uint_as_float(r0);
            v[2 * h + 1] = __uint_as_float(r1);
        }
        g_Wf4[t] = make_float4(v[0], v[1], v[2], v[3]);
    }
    if (t < nT) {
        int e = id_reduce[t];
        if (t == 0 || id_reduce[t - 1] != e) g_start[e] = t;
        if (t == nT - 1 || id_reduce[t + 1] != e) g_count[e] = Kidx[t] + 1;
    }
}

__device__ __forceinline__ unsigned tf32r(float x) {
    unsigned u; asm("cvt.rna.tf32.f32 %0, %1;" : "=r"(u) : "f"(x)); return u;
}

__device__ __forceinline__ void mma_tf32(float c[4], const unsigned a[4],
                                         unsigned b0, unsigned b1)
{
    asm volatile(
        "mma.sync.aligned.m16n8k8.row.col.f32.tf32.tf32.f32 "
        "{%0,%1,%2,%3},{%4,%5,%6,%7},{%8,%9},{%0,%1,%2,%3};"
        : "+f"(c[0]), "+f"(c[1]), "+f"(c[2]), "+f"(c[3])
        : "r"(a[0]), "r"(a[1]), "r"(a[2]), "r"(a[3]), "r"(b0), "r"(b1));
}

// One warp per edge, per-warp cp.async pipeline:
//   1. cp.async m (24 rows, zfilled beyond count) + sph into padded smem
//   2. rbf LDG batch -> cvt -> ra
//   3. P phase (W L1-resident, 64 mmas) -> p[8][4]   [overlaps cp.async]
//   4. wait_group; Q phase from conflict-free scalar LDS; Hadamard; store
__global__ void __launch_bounds__(128, 4)
main_kernel(const float* __restrict__ rbf,
            const float* __restrict__ sph,
            const float* __restrict__ m,
            float* __restrict__ out, int nEdges)
{
    __shared__ __align__(16) float m_s[4][KMAX * MROW];
    __shared__ __align__(16) float s_s[4][NSPH * SROW];

    const int lane = threadIdx.x & 31;
    const int wrp  = threadIdx.x >> 5;
    const int gid  = lane >> 2;   // 0..7
    const int tig  = lane & 3;    // 0..3

    const int e = blockIdx.x * 4 + wrp;
    if (e >= nEdges) return;

    const int st0 = g_start[e];
    const int ct0 = g_count[e];

    const unsigned msb = (unsigned)__cvta_generic_to_shared(&m_s[wrp][0]);
    const unsigned ssb = (unsigned)__cvta_generic_to_shared(&s_s[wrp][0]);

    // ---- 1. cp.async staging (coalesced 16B chunks) ----
    {
        const float* mg = m + (size_t)st0 * EMB;
        #pragma unroll
        for (int i = 0; i < 12; i++) {
            int chunk = i * 32 + lane;
            int row = chunk >> 4, c = chunk & 15;       // 16 chunks per 256B row
            unsigned dst = msb + (unsigned)(row * MROW + c * 4) * 4u;
            int srow = (row < ct0) ? row : 0;           // keep src in-bounds
            const float* src = mg + srow * EMB + c * 4;
            int sz = (row < ct0) ? 16 : 0;              // zfill padded rows
            asm volatile("cp.async.cg.shared.global [%0], [%1], 16, %2;"
                         :: "r"(dst), "l"(src), "r"(sz));
        }
        const float* sg = sph + (size_t)e * (NSPH * KMAX);
        #pragma unroll
        for (int i = 0; i < 3; i++) {
            int chunk = i * 32 + lane;
            int row = chunk / 6, c = chunk % 6;         // 6 chunks per 96B row
            unsigned dst = ssb + (unsigned)(row * SROW + c * 4) * 4u;
            const float* src = sg + row * KMAX + c * 4;
            asm volatile("cp.async.cg.shared.global [%0], [%1], 16;"
                         :: "r"(dst), "l"(src));
        }
        asm volatile("cp.async.commit_group;");
    }

    // ---- 2. rbf A-frags (raw f32 LDG batch, then cvt) ----
    unsigned ra[8][4];
    {
        float raf[8][4];
        const float* r0 = rbf + (size_t)e * (EMB * NSPH);
        #pragma unroll
        for (int kt = 0; kt < 8; kt++) {
            int i = kt * 8 + tig;
            raf[kt][0] = __ldg(&r0[i * NSPH + gid]);
            raf[kt][1] = __ldg(&r0[i * NSPH + gid + 8]);
            raf[kt][2] = __ldg(&r0[(i + 4) * NSPH + gid]);
            raf[kt][3] = __ldg(&r0[(i + 4) * NSPH + gid + 8]);
        }
        #pragma unroll
        for (int kt = 0; kt < 8; kt++)
            #pragma unroll
            for (int r = 0; r < 4; r++)
                ra[kt][r] = tf32r(raf[kt][r]);
    }

    // ---- 3. P phase: p[nt] = rbf^T x Wt tiles (overlaps cp.async) ----
    float p[8][4];
    #pragma unroll
    for (int nt = 0; nt < 8; nt++) {
        p[nt][0] = p[nt][1] = p[nt][2] = p[nt][3] = 0.f;
        #pragma unroll
        for (int j = 0; j < 4; j++) {
            float4 wf = __ldg(&g_Wf4[(j * 8 + nt) * 32 + lane]);
            mma_tf32(p[nt], ra[2 * j],     __float_as_uint(wf.x), __float_as_uint(wf.y));
            mma_tf32(p[nt], ra[2 * j + 1], __float_as_uint(wf.z), __float_as_uint(wf.w));
        }
    }

    // ---- 4. Q phase from smem (conflict-free scalar LDS) ----
    asm volatile("cp.async.wait_group 0;");
    __syncwarp();

    unsigned sa[3][4];
    {
        const float* sp = &s_s[wrp][0];
        #pragma unroll
        for (int kt = 0; kt < 3; kt++) {
            int t = kt * 8 + tig;
            sa[kt][0] = tf32r(sp[gid * SROW + t]);
            sa[kt][1] = tf32r(sp[(gid + 8) * SROW + t]);
            sa[kt][2] = tf32r(sp[gid * SROW + t + 4]);
            sa[kt][3] = tf32r(sp[(gid + 8) * SROW + t + 4]);
        }
    }

    const float* mp = &m_s[wrp][0];
    #pragma unroll
    for (int nt = 0; nt < 8; nt++) {
        float q[4] = {0.f, 0.f, 0.f, 0.f};
        #pragma unroll
        for (int kt = 0; kt < 3; kt++) {
            int t = kt * 8 + tig;
            unsigned b0 = tf32r(mp[t * MROW + nt * 8 + gid]);
            unsigned b1 = tf32r(mp[(t + 4) * MROW + nt * 8 + gid]);
            mma_tf32(q, sa[kt], b0, b1);
        }

        // c0:(s=gid, d=2tig) c1:(gid, 2tig+1) c2:(gid+8, 2tig) c3:(gid+8, 2tig+1)
        float h00 = p[nt][0] * q[0] + p[nt][2] * q[2];
        float h01 = p[nt][1] * q[1] + p[nt][3] * q[3];
        #pragma unroll
        for (int off = 4; off <= 16; off <<= 1) {
            h00 += __shfl_xor_sync(0xffffffffu, h00, off);
            h01 += __shfl_xor_sync(0xffffffffu, h01, off);
        }
        if (gid == 0)
            *(float2*)(out + (size_t)e * EMB + nt * 8 + 2 * tig) = make_float2(h00, h01);
    }
}

extern "C" void kernel_launch(void* const* d_in, const int* in_sizes, int n_in,
                              void* d_out, int out_size)
{
    const float* rbf  = (const float*)d_in[0];
    const float* sph  = (const float*)d_in[1];
    const float* m    = (const float*)d_in[2];
    const float* w    = (const float*)d_in[3];
    const int*   idr  = (const int*)d_in[4];
    const int*   kidx = (const int*)d_in[5];

    const int nEdges = in_sizes[0] / (EMB * NSPH);
    const int nT     = in_sizes[4];

    int prep_elems = nT > 1024 ? nT : 1024;
    prep_kernel<<<(prep_elems + 255) / 256, 256>>>(idr, kidx, w, nT);

    main_kernel<<<(nEdges + 3) / 4, 128>>>(rbf, sph, m, (float*)d_out, nEdges);
}

// round 14
// speedup vs baseline: 1.3468x; 1.2074x over previous
#include <cuda_runtime.h>

#define EMB   64
#define NSPH  16
#define KMAX  24
#define MAX_EDGES 131072

__device__ int    g_start[MAX_EDGES];
__device__ int    g_count[MAX_EDGES];
// W in mma-fragment order, 2 kt-frags packed per float4:
// g_Wf4[(j*8+nt)*32 + lane] = {b0(kt=2j), b1(kt=2j), b0(kt=2j+1), b1(kt=2j+1)}
__device__ float4 g_Wf4[32 * 32];

__global__ void prep_kernel(const int* __restrict__ id_reduce,
                            const int* __restrict__ Kidx,
                            const float* __restrict__ w, int nT)
{
    int t = blockIdx.x * blockDim.x + threadIdx.x;
    if (t < 1024) {
        int entry = t >> 5, lane = t & 31;
        int j  = entry >> 3, nt = entry & 7;
        int gid = lane >> 2, tig = lane & 3;
        int d = nt * 8 + gid;
        float v[4];
        #pragma unroll
        for (int h = 0; h < 2; h++) {
            int i = (2 * j + h) * 8 + tig;
            unsigned r0, r1;
            asm("cvt.rna.tf32.f32 %0, %1;" : "=r"(r0) : "f"(w[d * EMB + i]));
            asm("cvt.rna.tf32.f32 %0, %1;" : "=r"(r1) : "f"(w[d * EMB + i + 4]));
            v[2 * h]     = __uint_as_float(r0);
            v[2 * h + 1] = __uint_as_float(r1);
        }
        g_Wf4[t] = make_float4(v[0], v[1], v[2], v[3]);
    }
    if (t < nT) {
        int e = id_reduce[t];
        if (t == 0 || id_reduce[t - 1] != e) g_start[e] = t;
        if (t == nT - 1 || id_reduce[t + 1] != e) g_count[e] = Kidx[t] + 1;
    }
}

__device__ __forceinline__ unsigned tf32r(float x) {
    unsigned u; asm("cvt.rna.tf32.f32 %0, %1;" : "=r"(u) : "f"(x)); return u;
}

__device__ __forceinline__ void mma_tf32(float c[4], const unsigned a[4],
                                         unsigned b0, unsigned b1)
{
    asm volatile(
        "mma.sync.aligned.m16n8k8.row.col.f32.tf32.tf32.f32 "
        "{%0,%1,%2,%3},{%4,%5,%6,%7},{%8,%9},{%0,%1,%2,%3};"
        : "+f"(c[0]), "+f"(c[1]), "+f"(c[2]), "+f"(c[3])
        : "r"(a[0]), "r"(a[1]), "r"(a[2]), "r"(a[3]), "r"(b0), "r"(b1));
}

// One warp per edge. All streamed operands staged via cp.async.cg into
// XOR-swizzled (pad-free, conflict-free) smem:
//   rbf_s: rbf[i][s]  at i*16 + (s ^ ((i&2)<<2))   [s-xor-8 when i&2]
//   m_s:   m[t][d]    at t*64 + (d ^ ((t&3)*8)), rows >= count zfilled
//   s_s:   sph[s][k]  at s*24 + (k ^ (s&4))
// Pipeline: cp.async rbf (group0) -> cp.async m+sph (group1) ->
// wait 1 -> LDS ra, P phase (W L1-resident float4) -> wait 0 -> Q phase,
// Hadamard, xor-shfl s-reduction, store.
__global__ void __launch_bounds__(128, 4)
main_kernel(const float* __restrict__ rbf,
            const float* __restrict__ sph,
            const float* __restrict__ m,
            float* __restrict__ out, int nEdges)
{
    __shared__ __align__(16) float rbf_s[4][EMB * NSPH];   // 4KB/warp
    __shared__ __align__(16) float m_s[4][KMAX * EMB];     // 6KB/warp
    __shared__ __align__(16) float s_s[4][NSPH * KMAX];    // 1.5KB/warp

    const int lane = threadIdx.x & 31;
    const int wrp  = threadIdx.x >> 5;
    const int gid  = lane >> 2;   // 0..7
    const int tig  = lane & 3;    // 0..3

    const int e = blockIdx.x * 4 + wrp;
    if (e >= nEdges) return;

    const int st0 = g_start[e];
    const int ct0 = g_count[e];

    const unsigned rsb = (unsigned)__cvta_generic_to_shared(&rbf_s[wrp][0]);
    const unsigned msb = (unsigned)__cvta_generic_to_shared(&m_s[wrp][0]);
    const unsigned ssb = (unsigned)__cvta_generic_to_shared(&s_s[wrp][0]);

    // ---- group 0: rbf (4KB, 256 chunks); swizzle: chunk ^ (row&2) == s-xor-8 ----
    {
        const float* rg = rbf + (size_t)e * (EMB * NSPH);
        #pragma unroll
        for (int it = 0; it < 8; it++) {
            int chunk = it * 32 + lane;
            int row = chunk >> 2, c = chunk & 3;
            int dc = c ^ (row & 2);                      // float-xor-8 when i&2
            unsigned dst = rsb + (unsigned)(row * NSPH + dc * 4) * 4u;
            asm volatile("cp.async.cg.shared.global [%0], [%1], 16;"
                         :: "r"(dst), "l"(rg + chunk * 4));
        }
        asm volatile("cp.async.commit_group;");
    }

    // ---- group 1: m (zfilled) + sph ----
    {
        const float* mg = m + (size_t)st0 * EMB;
        #pragma unroll
        for (int it = 0; it < 12; it++) {
            int chunk = it * 32 + lane;
            int row = chunk >> 4, c = chunk & 15;
            int dc = c ^ ((row & 3) << 1);               // float-xor-(t&3)*8
            unsigned dst = msb + (unsigned)(row * EMB + dc * 4) * 4u;
            int srow = (row < ct0) ? row : 0;
            int sz   = (row < ct0) ? 16 : 0;
            asm volatile("cp.async.cg.shared.global [%0], [%1], 16, %2;"
                         :: "r"(dst), "l"(mg + srow * EMB + c * 4), "r"(sz));
        }
        const float* sg = sph + (size_t)e * (NSPH * KMAX);
        #pragma unroll
        for (int it = 0; it < 3; it++) {
            int chunk = it * 32 + lane;
            int row = chunk / 6, c = chunk % 6;
            int dc = c ^ ((row & 4) >> 2);               // float-xor-4 when s&4
            unsigned dst = ssb + (unsigned)(row * KMAX + dc * 4) * 4u;
            asm volatile("cp.async.cg.shared.global [%0], [%1], 16;"
                         :: "r"(dst), "l"(sg + row * KMAX + c * 4));
        }
        asm volatile("cp.async.commit_group;");
    }

    // ---- wait rbf; load ra from swizzled smem (conflict-free scalar LDS) ----
    asm volatile("cp.async.wait_group 1;");
    __syncwarp();

    unsigned ra[8][4];
    {
        const float* rp = &rbf_s[wrp][0];
        const int f = (tig & 2) << 2;                    // s-xor-8 when i&2 (i&2 == tig&2)
        #pragma unroll
        for (int kt = 0; kt < 8; kt++) {
            int i = kt * 8 + tig;
            ra[kt][0] = tf32r(rp[i * NSPH + (gid ^ f)]);
            ra[kt][1] = tf32r(rp[i * NSPH + ((gid + 8) ^ f)]);
            ra[kt][2] = tf32r(rp[(i + 4) * NSPH + (gid ^ f)]);
            ra[kt][3] = tf32r(rp[(i + 4) * NSPH + ((gid + 8) ^ f)]);
        }
    }

    // ---- P phase: p[nt] = rbf^T x Wt tiles (m/sph cp.async still in flight) ----
    float p[8][4];
    #pragma unroll
    for (int nt = 0; nt < 8; nt++) {
        p[nt][0] = p[nt][1] = p[nt][2] = p[nt][3] = 0.f;
        #pragma unroll
        for (int j = 0; j < 4; j++) {
            float4 wf = __ldg(&g_Wf4[(j * 8 + nt) * 32 + lane]);
            mma_tf32(p[nt], ra[2 * j],     __float_as_uint(wf.x), __float_as_uint(wf.y));
            mma_tf32(p[nt], ra[2 * j + 1], __float_as_uint(wf.z), __float_as_uint(wf.w));
        }
    }

    // ---- wait m+sph; Q phase from swizzled smem ----
    asm volatile("cp.async.wait_group 0;");
    __syncwarp();

    unsigned sa[3][4];
    {
        const float* sp = &s_s[wrp][0];
        const int h = gid & 4;
        #pragma unroll
        for (int kt = 0; kt < 3; kt++) {
            int t = kt * 8 + tig;
            sa[kt][0] = tf32r(sp[gid * KMAX + (t ^ h)]);
            sa[kt][1] = tf32r(sp[(gid + 8) * KMAX + (t ^ h)]);
            sa[kt][2] = tf32r(sp[gid * KMAX + ((t + 4) ^ h)]);
            sa[kt][3] = tf32r(sp[(gid + 8) * KMAX + ((t + 4) ^ h)]);
        }
    }

    const float* mp = &m_s[wrp][0];
    const int gsw = tig * 8;                              // m swizzle: d ^ ((t&3)*8), t&3 == tig
    #pragma unroll
    for (int nt = 0; nt < 8; nt++) {
        float q[4] = {0.f, 0.f, 0.f, 0.f};
        #pragma unroll
        for (int kt = 0; kt < 3; kt++) {
            int t = kt * 8 + tig;
            int col = (nt * 8 + gid) ^ gsw;
            unsigned b0 = tf32r(mp[t * EMB + col]);
            unsigned b1 = tf32r(mp[(t + 4) * EMB + col]);
            mma_tf32(q, sa[kt], b0, b1);
        }

        // c0:(s=gid, d=2tig) c1:(gid, 2tig+1) c2:(gid+8, 2tig) c3:(gid+8, 2tig+1)
        float h00 = p[nt][0] * q[0] + p[nt][2] * q[2];
        float h01 = p[nt][1] * q[1] + p[nt][3] * q[3];
        #pragma unroll
        for (int off = 4; off <= 16; off <<= 1) {
            h00 += __shfl_xor_sync(0xffffffffu, h00, off);
            h01 += __shfl_xor_sync(0xffffffffu, h01, off);
        }
        if (gid == 0)
            *(float2*)(out + (size_t)e * EMB + nt * 8 + 2 * tig) = make_float2(h00, h01);
    }
}

extern "C" void kernel_launch(void* const* d_in, const int* in_sizes, int n_in,
                              void* d_out, int out_size)
{
    const float* rbf  = (const float*)d_in[0];
    const float* sph  = (const float*)d_in[1];
    const float* m    = (const float*)d_in[2];
    const float* w    = (const float*)d_in[3];
    const int*   idr  = (const int*)d_in[4];
    const int*   kidx = (const int*)d_in[5];

    const int nEdges = in_sizes[0] / (EMB * NSPH);
    const int nT     = in_sizes[4];

    int prep_elems = nT > 1024 ? nT : 1024;
    prep_kernel<<<(prep_elems + 255) / 256, 256>>>(idr, kidx, w, nT);

    main_kernel<<<(nEdges + 3) / 4, 128>>>(rbf, sph, m, (float*)d_out, nEdges);
}